// round 5
// baseline (speedup 1.0000x reference)
#include <cuda_runtime.h>
#include <math.h>

#define B_ 128
#define T_ 512
#define D_ 512
#define U_ 512
#define N3 1536
#define RCTAS 128

typedef unsigned long long ull;

// ---- device scratch (static; allocation APIs banned) ----
__device__ float g_xproj[(size_t)T_ * B_ * N3];   // [t][b][n]
__device__ float g_h[2][U_ * B_];                 // [u][b]
__device__ float g_rh[U_ * B_];                   // [u][b]  (r*h)
__device__ float g_attnT[T_ * B_];                // [t][b]
__device__ unsigned g_bar;

// ---- helpers ----
__device__ __forceinline__ void cp16(float* sdst, const float* gsrc) {
    unsigned s = (unsigned)__cvta_generic_to_shared(sdst);
    asm volatile("cp.async.cg.shared.global [%0], [%1], 16;" :: "r"(s), "l"(gsrc));
}
template<int N> __device__ __forceinline__ void cpwait() {
    asm volatile("cp.async.wait_group %0;" :: "n"(N));
}
__device__ __forceinline__ ull pk2(float lo, float hi) {
    ull r; asm("mov.b64 %0, {%1, %2};" : "=l"(r) : "f"(lo), "f"(hi)); return r;
}
__device__ __forceinline__ float plo(ull v) {
    float a, b; asm("mov.b64 {%0, %1}, %2;" : "=f"(a), "=f"(b) : "l"(v)); return a;
}
__device__ __forceinline__ float phi(ull v) {
    float a, b; asm("mov.b64 {%0, %1}, %2;" : "=f"(a), "=f"(b) : "l"(v)); return b;
}
__device__ __forceinline__ void fma2(ull& d, ull a, ull b) {
    asm("fma.rn.f32x2 %0, %1, %2, %0;" : "+l"(d) : "l"(a), "l"(b));
}
__device__ __forceinline__ unsigned ldbar() {
    unsigned v;
    asm volatile("ld.acquire.gpu.global.u32 %0, [%1];" : "=r"(v) : "l"(&g_bar));
    return v;
}
__device__ __forceinline__ float hsig(float x) {
    return fminf(fmaxf(0.2f * x + 0.5f, 0.0f), 1.0f);
}

// ---- init ----
__global__ void init_k(const float* __restrict__ attn) {
    int i = blockIdx.x * 256 + threadIdx.x;
    if (i < U_ * B_) g_h[0][i] = 0.0f;
    if (i < T_ * B_) { int b = i >> 9, t = i & 511; g_attnT[t * B_ + b] = attn[i]; }
    if (i == 0) g_bar = 0u;
}

// ---- x_proj GEMM: g_xproj[t][b][n] = inputs[b][t][:] . W[:,n] + bias[n] ----
__global__ void __launch_bounds__(256) xproj_k(const float* __restrict__ A,
                                               const float* __restrict__ W,
                                               const float* __restrict__ bias) {
    __shared__ float As[16][132];
    __shared__ float Bs[16][132];
    const int tid = threadIdx.x;
    const int m0 = blockIdx.x * 128, n0 = blockIdx.y * 128;
    const int tx = tid & 15, ty = tid >> 4;
    ull acc[8][4];
    #pragma unroll
    for (int i = 0; i < 8; i++)
        #pragma unroll
        for (int j = 0; j < 4; j++) acc[i][j] = 0ull;

    for (int kt = 0; kt < D_; kt += 16) {
        {   // A tile 128x16 -> As[k][m] (transposed)
            int r = tid >> 1, c = (tid & 1) * 8;
            const float* src = A + (size_t)(m0 + r) * D_ + kt + c;
            float4 v0 = *(const float4*)(src);
            float4 v1 = *(const float4*)(src + 4);
            As[c + 0][r] = v0.x; As[c + 1][r] = v0.y; As[c + 2][r] = v0.z; As[c + 3][r] = v0.w;
            As[c + 4][r] = v1.x; As[c + 5][r] = v1.y; As[c + 6][r] = v1.z; As[c + 7][r] = v1.w;
        }
        {   // B tile 16x128
            int r = tid >> 5, c = (tid & 31) * 4;
            #pragma unroll
            for (int j = 0; j < 2; j++)
                *(float4*)&Bs[r + j * 8][c] = *(const float4*)(W + (size_t)(kt + r + j * 8) * N3 + n0 + c);
        }
        __syncthreads();
        #pragma unroll
        for (int k = 0; k < 16; k++) {
            float av[8];
            *(float4*)(av)     = *(float4*)&As[k][ty * 8];
            *(float4*)(av + 4) = *(float4*)&As[k][ty * 8 + 4];
            ulonglong2 b01 = *(ulonglong2*)&Bs[k][tx * 8];
            ulonglong2 b23 = *(ulonglong2*)&Bs[k][tx * 8 + 4];
            #pragma unroll
            for (int i = 0; i < 8; i++) {
                ull ad = pk2(av[i], av[i]);
                fma2(acc[i][0], ad, b01.x);
                fma2(acc[i][1], ad, b01.y);
                fma2(acc[i][2], ad, b23.x);
                fma2(acc[i][3], ad, b23.y);
            }
        }
        __syncthreads();
    }
    #pragma unroll
    for (int i = 0; i < 8; i++) {
        int m = m0 + ty * 8 + i, bb = m >> 9, t = m & 511;
        float* dst = g_xproj + (size_t)(t * B_ + bb) * N3 + n0 + tx * 8;
        float o[8];
        #pragma unroll
        for (int j = 0; j < 4; j++) {
            o[2 * j]     = plo(acc[i][j]) + bias[n0 + tx * 8 + 2 * j];
            o[2 * j + 1] = phi(acc[i][j]) + bias[n0 + tx * 8 + 2 * j + 1];
        }
        *(float4*)(dst)     = *(float4*)(o);
        *(float4*)(dst + 4) = *(float4*)(o + 4);
    }
}

// ---- persistent two-phase GRU recurrence ----
// 128 CTAs x 256 threads. thread = (b = tid&127, kk = tid>>7). CTA owns u in [u0,u0+4).
// smem: sRzr[512][4] ull (z/r col-pairs), sRh[512][2] ull, sS[2][64*128] float staging.
#define REC_SMEM ((3072 * 8) + (2 * 8192 * 4))

__device__ __forceinline__ void stage64(float* dst, const float* src, int tid) {
    #pragma unroll
    for (int j = 0; j < 8; j++) {
        int idx = (tid + j * 256) * 4;
        cp16(dst + idx, src + idx);
    }
    asm volatile("cp.async.commit_group;");
}

__global__ void __launch_bounds__(256, 1) rec_k(const float* __restrict__ RK,
                                                float* __restrict__ out) {
    extern __shared__ ull smb[];
    ull* sRzr = smb;                       // 2048 ull
    ull* sRh  = smb + 2048;                // 1024 ull
    float* sS = (float*)(smb + 3072);      // 2 x 8192 floats
    const int tid = threadIdx.x;
    const int b = tid & 127, kk = tid >> 7;
    const int u0 = blockIdx.x * 4;
    const int up = u0 + 2 * kk;            // this thread's u-pair base

    // preload R columns (packed pairs)
    for (int k = tid; k < 512; k += 256) {
        const float* rk = RK + (size_t)k * N3;
        sRzr[k * 4 + 0] = pk2(rk[u0],        rk[u0 + 1]);
        sRzr[k * 4 + 1] = pk2(rk[512 + u0],  rk[512 + u0 + 1]);
        sRzr[k * 4 + 2] = pk2(rk[u0 + 2],    rk[u0 + 3]);
        sRzr[k * 4 + 3] = pk2(rk[512 + u0 + 2], rk[512 + u0 + 3]);
        sRh[k * 2 + 0]  = pk2(rk[1024 + u0],     rk[1024 + u0 + 1]);
        sRh[k * 2 + 1]  = pk2(rk[1024 + u0 + 2], rk[1024 + u0 + 3]);
    }
    __syncthreads();

    int cur = 0;
    for (int t = 0; t < T_; t++) {
        const float* hsrc = g_h[cur];

        // ---------- phase 1: az, ar = h @ [Rz|Rr] cols ----------
        stage64(sS, hsrc, tid);
        ull az = 0ull, ar = 0ull;
        for (int c = 0; c < 8; c++) {
            if (c < 7) { stage64(sS + ((c + 1) & 1) * 8192, hsrc + (c + 1) * 8192, tid); cpwait<1>(); }
            else cpwait<0>();
            __syncthreads();
            const float* hb = sS + (c & 1) * 8192;
            const ull* rr = sRzr + (size_t)c * 64 * 4 + kk * 2;
            #pragma unroll 16
            for (int k = 0; k < 64; k++) {
                float hv = hb[k * 128 + b];
                ull hd = pk2(hv, hv);
                ulonglong2 zr = *(const ulonglong2*)(rr + k * 4);
                fma2(az, hd, zr.x);
                fma2(ar, hd, zr.y);
            }
            __syncthreads();
        }

        const float* xp = g_xproj + ((size_t)t * B_ + b) * N3 + up;
        float2 xz = *(const float2*)(xp);
        float2 xr = *(const float2*)(xp + 512);
        float2 xh = *(const float2*)(xp + 1024);
        float hp0 = hsrc[up * 128 + b];
        float hp1 = hsrc[(up + 1) * 128 + b];
        float z0 = hsig(xz.x + plo(az)), z1 = hsig(xz.y + phi(az));
        float r0 = hsig(xr.x + plo(ar)), r1 = hsig(xr.y + phi(ar));
        g_rh[up * 128 + b]       = r0 * hp0;
        g_rh[(up + 1) * 128 + b] = r1 * hp1;

        __threadfence();
        __syncthreads();
        if (tid == 0) {
            atomicAdd(&g_bar, 1u);
            unsigned tgt = (unsigned)(2 * t + 1) * RCTAS;
            while (ldbar() < tgt) { }
        }
        __syncthreads();

        // ---------- phase 2: ah = (r.h) @ Rh cols ----------
        stage64(sS, g_rh, tid);
        ull ah = 0ull;
        for (int c = 0; c < 8; c++) {
            if (c < 7) { stage64(sS + ((c + 1) & 1) * 8192, g_rh + (c + 1) * 8192, tid); cpwait<1>(); }
            else cpwait<0>();
            __syncthreads();
            const float* hb = sS + (c & 1) * 8192;
            const ull* rr = sRh + (size_t)c * 64 * 2 + kk;
            #pragma unroll 16
            for (int k = 0; k < 64; k++) {
                float rv = hb[k * 128 + b];
                ull rd = pk2(rv, rv);
                fma2(ah, rd, rr[k * 2]);
            }
            __syncthreads();
        }

        float a = g_attnT[t * B_ + b];
        float hh0 = tanhf(xh.x + plo(ah));
        float hh1 = tanhf(xh.y + phi(ah));
        float hn0 = z0 * hp0 + (1.0f - z0) * hh0;
        float hn1 = z1 * hp1 + (1.0f - z1) * hh1;
        hn0 = a * hn0 + (1.0f - a) * hp0;
        hn1 = a * hn1 + (1.0f - a) * hp1;
        float* hd = g_h[cur ^ 1];
        hd[up * 128 + b]       = hn0;
        hd[(up + 1) * 128 + b] = hn1;
        if (t == T_ - 1) {
            out[b * U_ + up]     = hn0;
            out[b * U_ + up + 1] = hn1;
        }

        __threadfence();
        __syncthreads();
        if (tid == 0) {
            atomicAdd(&g_bar, 1u);
            unsigned tgt = (unsigned)(2 * t + 2) * RCTAS;
            while (ldbar() < tgt) { }
        }
        __syncthreads();
        cur ^= 1;
    }
}

extern "C" void kernel_launch(void* const* d_in, const int* in_sizes, int n_in,
                              void* d_out, int out_size) {
    const float* inputs = (const float*)d_in[0];
    const float* attn   = (const float*)d_in[1];
    const float* Wk     = (const float*)d_in[2];
    const float* RK     = (const float*)d_in[3];
    const float* bias   = (const float*)d_in[4];
    cudaFuncSetAttribute(rec_k, cudaFuncAttributeMaxDynamicSharedMemorySize, REC_SMEM);
    init_k<<<256, 256>>>(attn);
    xproj_k<<<dim3(512, 12), 256>>>(inputs, Wk, bias);
    rec_k<<<RCTAS, 256, REC_SMEM>>>(RK, (float*)d_out);
}

// round 8
// speedup vs baseline: 1.1615x; 1.1615x over previous
#include <cuda_runtime.h>
#include <cuda_bf16.h>
#include <math.h>
#include <stdint.h>

typedef unsigned u32; typedef unsigned long long ull;
#define NCTA 64
#define ABUF 34816
#define AHI(b) ((b)*69632)
#define SB1  139264
#define SB1L 155904
#define SB2  172544
#define SB2L 180864
#define SMEM_TOT 189184

__device__ float g_xproj[(size_t)512*128*1536];
__device__ __nv_bfloat16 g_hhi[65536], g_hlo[65536], g_rhhi[65536], g_rhlo[65536];
__device__ unsigned g_bar;

__device__ __forceinline__ void cp16(void* s, const void* g) {
    u32 a = (u32)__cvta_generic_to_shared(s);
    asm volatile("cp.async.cg.shared.global [%0], [%1], 16;" :: "r"(a), "l"(g));
}
template<int N> __device__ __forceinline__ void cpwait() { asm volatile("cp.async.wait_group %0;" :: "n"(N)); }
__device__ __forceinline__ void cpcommit() { asm volatile("cp.async.commit_group;"); }
__device__ __forceinline__ unsigned ldbar() {
    unsigned v; asm volatile("ld.acquire.gpu.global.u32 %0, [%1];" : "=r"(v) : "l"(&g_bar)); return v;
}
__device__ __forceinline__ float hsig(float x) { return fminf(fmaxf(0.2f*x + 0.5f, 0.f), 1.f); }
__device__ __forceinline__ void mma16(float* c, u32 a0, u32 a1, u32 a2, u32 a3, u32 b0, u32 b1) {
    asm volatile("mma.sync.aligned.m16n8k16.row.col.f32.bf16.bf16.f32 "
        "{%0,%1,%2,%3},{%4,%5,%6,%7},{%8,%9},{%0,%1,%2,%3};"
        : "+f"(c[0]), "+f"(c[1]), "+f"(c[2]), "+f"(c[3])
        : "r"(a0), "r"(a1), "r"(a2), "r"(a3), "r"(b0), "r"(b1));
}
__device__ __forceinline__ void wr_pair(__nv_bfloat16* Ah, __nv_bfloat16* Al, int off, float v0, float v1) {
    __nv_bfloat16 h0 = __float2bfloat16(v0), h1 = __float2bfloat16(v1);
    __nv_bfloat16 l0 = __float2bfloat16(v0 - __bfloat162float(h0));
    __nv_bfloat16 l1 = __float2bfloat16(v1 - __bfloat162float(h1));
    *(u32*)(Ah + off) = (u32)__bfloat16_as_ushort(h0) | ((u32)__bfloat16_as_ushort(h1) << 16);
    *(u32*)(Al + off) = (u32)__bfloat16_as_ushort(l0) | ((u32)__bfloat16_as_ushort(l1) << 16);
}

__global__ void init_k(const float*) {
    int i = blockIdx.x * 256 + threadIdx.x;
    if (i < 65536) { g_hhi[i] = __float2bfloat16(0.f); g_hlo[i] = __float2bfloat16(0.f); }
    if (i == 0) g_bar = 0u;
}

// ---- verified f32x2 SIMT xproj (round 4) ----
__device__ __forceinline__ ull pk2(float lo, float hi) { ull r; asm("mov.b64 %0,{%1,%2};" : "=l"(r) : "f"(lo), "f"(hi)); return r; }
__device__ __forceinline__ float plo(ull v) { float a, b; asm("mov.b64 {%0,%1},%2;" : "=f"(a), "=f"(b) : "l"(v)); return a; }
__device__ __forceinline__ float phi(ull v) { float a, b; asm("mov.b64 {%0,%1},%2;" : "=f"(a), "=f"(b) : "l"(v)); return b; }
__device__ __forceinline__ void fma2(ull& d, ull a, ull b) { asm("fma.rn.f32x2 %0,%1,%2,%0;" : "+l"(d) : "l"(a), "l"(b)); }

__global__ void __launch_bounds__(256) xproj_k(const float* __restrict__ A, const float* __restrict__ W,
                                               const float* __restrict__ bias) {
    __shared__ float As[16][132], Bs[16][132];
    const int tid = threadIdx.x, m0 = blockIdx.x * 128, n0 = blockIdx.y * 128;
    const int tx = tid & 15, ty = tid >> 4;
    ull acc[8][4];
    #pragma unroll
    for (int i = 0; i < 8; i++) { acc[i][0] = acc[i][1] = acc[i][2] = acc[i][3] = 0ull; }
    for (int kt = 0; kt < 512; kt += 16) {
        int r = tid >> 1, c = (tid & 1) * 8;
        const float* src = A + (size_t)(m0 + r) * 512 + kt + c;
        float4 v0 = *(const float4*)src, v1 = *(const float4*)(src + 4);
        As[c][r] = v0.x; As[c+1][r] = v0.y; As[c+2][r] = v0.z; As[c+3][r] = v0.w;
        As[c+4][r] = v1.x; As[c+5][r] = v1.y; As[c+6][r] = v1.z; As[c+7][r] = v1.w;
        int r2 = tid >> 5, c2 = (tid & 31) * 4;
        #pragma unroll
        for (int j = 0; j < 2; j++)
            *(float4*)&Bs[r2 + j*8][c2] = *(const float4*)(W + (size_t)(kt + r2 + j*8) * 1536 + n0 + c2);
        __syncthreads();
        #pragma unroll
        for (int k = 0; k < 16; k++) {
            float av[8];
            *(float4*)av = *(float4*)&As[k][ty*8]; *(float4*)(av+4) = *(float4*)&As[k][ty*8+4];
            ulonglong2 b01 = *(ulonglong2*)&Bs[k][tx*8], b23 = *(ulonglong2*)&Bs[k][tx*8+4];
            #pragma unroll
            for (int i = 0; i < 8; i++) {
                ull ad = pk2(av[i], av[i]);
                fma2(acc[i][0], ad, b01.x); fma2(acc[i][1], ad, b01.y);
                fma2(acc[i][2], ad, b23.x); fma2(acc[i][3], ad, b23.y);
            }
        }
        __syncthreads();
    }
    #pragma unroll
    for (int i = 0; i < 8; i++) {
        int m = m0 + ty*8 + i, bb = m >> 9, t = m & 511;
        float* dst = g_xproj + (size_t)(t * 128 + bb) * 1536 + n0 + tx*8;
        float o[8];
        #pragma unroll
        for (int j = 0; j < 4; j++) {
            o[2*j]   = plo(acc[i][j]) + bias[n0 + tx*8 + 2*j];
            o[2*j+1] = phi(acc[i][j]) + bias[n0 + tx*8 + 2*j + 1];
        }
        *(float4*)dst = *(float4*)o; *(float4*)(dst+4) = *(float4*)(o+4);
    }
}

// ---- recurrence ----
__device__ __forceinline__ void stageA(char* sm, int kc, const __nv_bfloat16* ghi,
                                       const __nv_bfloat16* glo, int tid) {
    char* dh = sm + AHI(kc & 1);
    #pragma unroll
    for (int j = 0; j < 8; j++) {
        int v = tid + j * 256, b = v >> 4, u = v & 15;
        int so = b * 272 + u * 16, go = b * 512 + kc * 128 + u * 8;
        cp16(dh + so, ghi + go);
        cp16(dh + ABUF + so, glo + go);
    }
    cpcommit();
}

__device__ __forceinline__ void gbar(int tid, unsigned tgt) {
    __threadfence(); __syncthreads();
    if (tid == 0) { atomicAdd(&g_bar, 1u); while (ldbar() < tgt * NCTA) {} }
    __syncthreads();
}

template<int NBLK>
__device__ __forceinline__ void mma_phase(char* sm, const __nv_bfloat16* ghi, const __nv_bfloat16* glo,
                                          int sb, int sbl, float (*acc)[4], int tid, int arow, int gr, int tig) {
    stageA(sm, 0, ghi, glo, tid);
    for (int c = 0; c < 4; c++) {
        if (c < 3) { stageA(sm, c + 1, ghi, glo, tid); cpwait<1>(); } else cpwait<0>();
        __syncthreads();
        const char* ah = sm + AHI(c & 1) + arow * 272 + tig * 4;
        #pragma unroll
        for (int ks = 0; ks < 8; ks++) {
            int ko = ks * 32;
            u32 a0 = *(const u32*)(ah + ko),        a1 = *(const u32*)(ah + ko + 8*272);
            u32 a2 = *(const u32*)(ah + ko + 16),   a3 = *(const u32*)(ah + ko + 16 + 8*272);
            u32 l0 = *(const u32*)(ah + ABUF + ko),      l1 = *(const u32*)(ah + ABUF + ko + 8*272);
            u32 l2 = *(const u32*)(ah + ABUF + ko + 16), l3 = *(const u32*)(ah + ABUF + ko + 16 + 8*272);
            #pragma unroll
            for (int nb = 0; nb < NBLK; nb++) {
                int bo = (nb * 8 + gr) * 1040 + c * 256 + ks * 32 + tig * 4;
                u32 b0 = *(const u32*)(sm + sb + bo),  u32b1 = *(const u32*)(sm + sb + bo + 16);
                u32 c0 = *(const u32*)(sm + sbl + bo), c1 = *(const u32*)(sm + sbl + bo + 16);
                mma16(acc[nb], a0, a1, a2, a3, b0, u32b1);
                mma16(acc[nb], l0, l1, l2, l3, b0, u32b1);
                mma16(acc[nb], a0, a1, a2, a3, c0, c1);
            }
        }
        __syncthreads();
    }
}

__global__ void __launch_bounds__(256, 1) rec_k(const float* __restrict__ RK,
                                                const float* __restrict__ attn,
                                                float* __restrict__ out) {
    extern __shared__ char sm[];
    const int tid = threadIdx.x, w = tid >> 5, lane = tid & 31, gr = lane >> 2, tig = lane & 3;
    const int u0 = blockIdx.x * 8;
    for (int idx = tid; idx < 16 * 512; idx += 256) {
        int n = idx >> 9, k = idx & 511;
        int col = n < 8 ? (u0 + n) : (512 + u0 + n - 8);
        float v = RK[(size_t)k * 1536 + col];
        __nv_bfloat16 h = __float2bfloat16(v), l = __float2bfloat16(v - __bfloat162float(h));
        *(__nv_bfloat16*)(sm + SB1 + n*1040 + k*2) = h;
        *(__nv_bfloat16*)(sm + SB1L + n*1040 + k*2) = l;
    }
    for (int idx = tid; idx < 8 * 512; idx += 256) {
        int n = idx >> 9, k = idx & 511;
        float v = RK[(size_t)k * 1536 + 1024 + u0 + n];
        __nv_bfloat16 h = __float2bfloat16(v), l = __float2bfloat16(v - __bfloat162float(h));
        *(__nv_bfloat16*)(sm + SB2 + n*1040 + k*2) = h;
        *(__nv_bfloat16*)(sm + SB2L + n*1040 + k*2) = l;
    }
    __syncthreads();

    const int b0r = w * 16 + gr, b1r = b0r + 8, arow = b0r;
    const int uc = u0 + tig * 2;
    float h00 = 0.f, h01 = 0.f, h10 = 0.f, h11 = 0.f;
    float z00, z01, z10, z11;

    for (int t = 0; t < 512; t++) {
        float a1[2][4] = {{0,0,0,0},{0,0,0,0}};
        mma_phase<2>(sm, g_hhi, g_hlo, SB1, SB1L, a1, tid, arow, gr, tig);
        {
            const float* x0 = g_xproj + ((size_t)t * 128 + b0r) * 1536 + uc;
            const float* x1 = g_xproj + ((size_t)t * 128 + b1r) * 1536 + uc;
            float2 xz0 = *(const float2*)x0, xr0 = *(const float2*)(x0 + 512);
            float2 xz1 = *(const float2*)x1, xr1 = *(const float2*)(x1 + 512);
            z00 = hsig(xz0.x + a1[0][0]); z01 = hsig(xz0.y + a1[0][1]);
            z10 = hsig(xz1.x + a1[0][2]); z11 = hsig(xz1.y + a1[0][3]);
            float r00 = hsig(xr0.x + a1[1][0]), r01 = hsig(xr0.y + a1[1][1]);
            float r10 = hsig(xr1.x + a1[1][2]), r11 = hsig(xr1.y + a1[1][3]);
            wr_pair(g_rhhi, g_rhlo, b0r * 512 + uc, r00 * h00, r01 * h01);
            wr_pair(g_rhhi, g_rhlo, b1r * 512 + uc, r10 * h10, r11 * h11);
        }
        gbar(tid, 2 * t + 1);

        float a2[1][4] = {{0,0,0,0}};
        mma_phase<1>(sm, g_rhhi, g_rhlo, SB2, SB2L, a2, tid, arow, gr, tig);
        {
            const float* x0 = g_xproj + ((size_t)t * 128 + b0r) * 1536 + 1024 + uc;
            const float* x1 = g_xproj + ((size_t)t * 128 + b1r) * 1536 + 1024 + uc;
            float2 xh0 = *(const float2*)x0, xh1 = *(const float2*)x1;
            float av0 = attn[b0r * 512 + t], av1 = attn[b1r * 512 + t];
            float hh;
            hh = tanhf(xh0.x + a2[0][0]); hh = z00 * h00 + (1.f - z00) * hh; h00 = av0 * hh + (1.f - av0) * h00;
            hh = tanhf(xh0.y + a2[0][1]); hh = z01 * h01 + (1.f - z01) * hh; h01 = av0 * hh + (1.f - av0) * h01;
            hh = tanhf(xh1.x + a2[0][2]); hh = z10 * h10 + (1.f - z10) * hh; h10 = av1 * hh + (1.f - av1) * h10;
            hh = tanhf(xh1.y + a2[0][3]); hh = z11 * h11 + (1.f - z11) * hh; h11 = av1 * hh + (1.f - av1) * h11;
            wr_pair(g_hhi, g_hlo, b0r * 512 + uc, h00, h01);
            wr_pair(g_hhi, g_hlo, b1r * 512 + uc, h10, h11);
            if (t == 511) {
                *(float2*)(out + b0r * 512 + uc) = make_float2(h00, h01);
                *(float2*)(out + b1r * 512 + uc) = make_float2(h10, h11);
            }
        }
        gbar(tid, 2 * t + 2);
    }
}

extern "C" void kernel_launch(void* const* d_in, const int* in_sizes, int n_in,
                              void* d_out, int out_size) {
    cudaFuncSetAttribute(rec_k, cudaFuncAttributeMaxDynamicSharedMemorySize, SMEM_TOT);
    init_k<<<256, 256>>>((const float*)d_in[1]);
    xproj_k<<<dim3(512, 12), 256>>>((const float*)d_in[0], (const float*)d_in[2], (const float*)d_in[4]);
    rec_k<<<NCTA, 256, SMEM_TOT>>>((const float*)d_in[3], (const float*)d_in[1], (float*)d_out);
}

// round 9
// speedup vs baseline: 1.4680x; 1.2638x over previous
#include <cuda_runtime.h>
#include <cuda_bf16.h>
#include <math.h>
#include <stdint.h>

typedef unsigned u32; typedef unsigned long long ull;
#define NCTA 64
#define ABUF 34816
#define AHI(b) ((b)*ABUF)
#define SB1  69632
#define SB1L 86272
#define SB2  102912
#define SB2L 111232
#define SMEM_TOT 119552

__device__ float g_xproj[(size_t)512*128*1536];
__device__ __nv_bfloat16 g_hhi[65536], g_rhhi[65536];
__device__ unsigned g_bar;

__device__ __forceinline__ void cp16(void* s, const void* g) {
    u32 a = (u32)__cvta_generic_to_shared(s);
    asm volatile("cp.async.cg.shared.global [%0], [%1], 16;" :: "r"(a), "l"(g));
}
template<int N> __device__ __forceinline__ void cpwait() { asm volatile("cp.async.wait_group %0;" :: "n"(N)); }
__device__ __forceinline__ void cpcommit() { asm volatile("cp.async.commit_group;"); }
__device__ __forceinline__ unsigned ldbar() {
    unsigned v; asm volatile("ld.acquire.gpu.global.u32 %0, [%1];" : "=r"(v) : "l"(&g_bar)); return v;
}
__device__ __forceinline__ float hsig(float x) { return fminf(fmaxf(0.2f*x + 0.5f, 0.f), 1.f); }
__device__ __forceinline__ void mma16(float* c, u32 a0, u32 a1, u32 a2, u32 a3, u32 b0, u32 b1) {
    asm volatile("mma.sync.aligned.m16n8k16.row.col.f32.bf16.bf16.f32 "
        "{%0,%1,%2,%3},{%4,%5,%6,%7},{%8,%9},{%0,%1,%2,%3};"
        : "+f"(c[0]), "+f"(c[1]), "+f"(c[2]), "+f"(c[3])
        : "r"(a0), "r"(a1), "r"(a2), "r"(a3), "r"(b0), "r"(b1));
}
__device__ __forceinline__ void wr_hi(__nv_bfloat16* Ah, int off, float v0, float v1) {
    __nv_bfloat16 h0 = __float2bfloat16(v0), h1 = __float2bfloat16(v1);
    *(u32*)(Ah + off) = (u32)__bfloat16_as_ushort(h0) | ((u32)__bfloat16_as_ushort(h1) << 16);
}

__global__ void init_k(const float*) {
    int i = blockIdx.x * 256 + threadIdx.x;
    if (i < 65536) g_hhi[i] = __float2bfloat16(0.f);
    if (i == 0) g_bar = 0u;
}

// ---- verified f32x2 SIMT xproj (round 4) ----
__device__ __forceinline__ ull pk2(float lo, float hi) { ull r; asm("mov.b64 %0,{%1,%2};" : "=l"(r) : "f"(lo), "f"(hi)); return r; }
__device__ __forceinline__ float plo(ull v) { float a, b; asm("mov.b64 {%0,%1},%2;" : "=f"(a), "=f"(b) : "l"(v)); return a; }
__device__ __forceinline__ float phi(ull v) { float a, b; asm("mov.b64 {%0,%1},%2;" : "=f"(a), "=f"(b) : "l"(v)); return b; }
__device__ __forceinline__ void fma2(ull& d, ull a, ull b) { asm("fma.rn.f32x2 %0,%1,%2,%0;" : "+l"(d) : "l"(a), "l"(b)); }

__global__ void __launch_bounds__(256) xproj_k(const float* __restrict__ A, const float* __restrict__ W,
                                               const float* __restrict__ bias) {
    __shared__ float As[16][132], Bs[16][132];
    const int tid = threadIdx.x, m0 = blockIdx.x * 128, n0 = blockIdx.y * 128;
    const int tx = tid & 15, ty = tid >> 4;
    ull acc[8][4];
    #pragma unroll
    for (int i = 0; i < 8; i++) { acc[i][0] = acc[i][1] = acc[i][2] = acc[i][3] = 0ull; }
    for (int kt = 0; kt < 512; kt += 16) {
        int r = tid >> 1, c = (tid & 1) * 8;
        const float* src = A + (size_t)(m0 + r) * 512 + kt + c;
        float4 v0 = *(const float4*)src, v1 = *(const float4*)(src + 4);
        As[c][r] = v0.x; As[c+1][r] = v0.y; As[c+2][r] = v0.z; As[c+3][r] = v0.w;
        As[c+4][r] = v1.x; As[c+5][r] = v1.y; As[c+6][r] = v1.z; As[c+7][r] = v1.w;
        int r2 = tid >> 5, c2 = (tid & 31) * 4;
        #pragma unroll
        for (int j = 0; j < 2; j++)
            *(float4*)&Bs[r2 + j*8][c2] = *(const float4*)(W + (size_t)(kt + r2 + j*8) * 1536 + n0 + c2);
        __syncthreads();
        #pragma unroll
        for (int k = 0; k < 16; k++) {
            float av[8];
            *(float4*)av = *(float4*)&As[k][ty*8]; *(float4*)(av+4) = *(float4*)&As[k][ty*8+4];
            ulonglong2 b01 = *(ulonglong2*)&Bs[k][tx*8], b23 = *(ulonglong2*)&Bs[k][tx*8+4];
            #pragma unroll
            for (int i = 0; i < 8; i++) {
                ull ad = pk2(av[i], av[i]);
                fma2(acc[i][0], ad, b01.x); fma2(acc[i][1], ad, b01.y);
                fma2(acc[i][2], ad, b23.x); fma2(acc[i][3], ad, b23.y);
            }
        }
        __syncthreads();
    }
    #pragma unroll
    for (int i = 0; i < 8; i++) {
        int m = m0 + ty*8 + i, bb = m >> 9, t = m & 511;
        float* dst = g_xproj + (size_t)(t * 128 + bb) * 1536 + n0 + tx*8;
        float o[8];
        #pragma unroll
        for (int j = 0; j < 4; j++) {
            o[2*j]   = plo(acc[i][j]) + bias[n0 + tx*8 + 2*j];
            o[2*j+1] = phi(acc[i][j]) + bias[n0 + tx*8 + 2*j + 1];
        }
        *(float4*)dst = *(float4*)o; *(float4*)(dst+4) = *(float4*)(o+4);
    }
}

// ---- recurrence ----
__device__ __forceinline__ void stageA(char* sm, int kc, const __nv_bfloat16* ghi, int tid) {
    char* dh = sm + AHI(kc & 1);
    #pragma unroll
    for (int j = 0; j < 8; j++) {
        int v = tid + j * 256, b = v >> 4, u = v & 15;
        cp16(dh + b * 272 + u * 16, ghi + b * 512 + kc * 128 + u * 8);
    }
    cpcommit();
}

__device__ __forceinline__ void gbar(int tid, unsigned tgt) {
    __threadfence(); __syncthreads();
    if (tid == 0) { atomicAdd(&g_bar, 1u); while (ldbar() < tgt * NCTA) {} }
    __syncthreads();
}

template<int NBLK>
__device__ __forceinline__ void mma_phase(char* sm, const __nv_bfloat16* ghi,
                                          int sb, int sbl, float (*acc)[4], int tid, int arow, int gr, int tig) {
    stageA(sm, 0, ghi, tid);
    for (int c = 0; c < 4; c++) {
        if (c < 3) { stageA(sm, c + 1, ghi, tid); cpwait<1>(); } else cpwait<0>();
        __syncthreads();
        const char* ah = sm + AHI(c & 1) + arow * 272 + tig * 4;
        #pragma unroll
        for (int ks = 0; ks < 8; ks++) {
            int ko = ks * 32;
            u32 a0 = *(const u32*)(ah + ko),      a1 = *(const u32*)(ah + ko + 8*272);
            u32 a2 = *(const u32*)(ah + ko + 16), a3 = *(const u32*)(ah + ko + 16 + 8*272);
            #pragma unroll
            for (int nb = 0; nb < NBLK; nb++) {
                int bo = (nb * 8 + gr) * 1040 + c * 256 + ks * 32 + tig * 4;
                u32 b0 = *(const u32*)(sm + sb + bo),  b1 = *(const u32*)(sm + sb + bo + 16);
                u32 c0 = *(const u32*)(sm + sbl + bo), c1 = *(const u32*)(sm + sbl + bo + 16);
                mma16(acc[nb], a0, a1, a2, a3, b0, b1);
                mma16(acc[nb], a0, a1, a2, a3, c0, c1);
            }
        }
        __syncthreads();
    }
}

__global__ void __launch_bounds__(256, 1) rec_k(const float* __restrict__ RK,
                                                const float* __restrict__ attn,
                                                float* __restrict__ out) {
    extern __shared__ char sm[];
    const int tid = threadIdx.x, w = tid >> 5, lane = tid & 31, gr = lane >> 2, tig = lane & 3;
    const int u0 = blockIdx.x * 8;
    for (int idx = tid; idx < 16 * 512; idx += 256) {
        int n = idx >> 9, k = idx & 511;
        int col = n < 8 ? (u0 + n) : (512 + u0 + n - 8);
        float v = RK[(size_t)k * 1536 + col];
        __nv_bfloat16 h = __float2bfloat16(v), l = __float2bfloat16(v - __bfloat162float(h));
        *(__nv_bfloat16*)(sm + SB1 + n*1040 + k*2) = h;
        *(__nv_bfloat16*)(sm + SB1L + n*1040 + k*2) = l;
    }
    for (int idx = tid; idx < 8 * 512; idx += 256) {
        int n = idx >> 9, k = idx & 511;
        float v = RK[(size_t)k * 1536 + 1024 + u0 + n];
        __nv_bfloat16 h = __float2bfloat16(v), l = __float2bfloat16(v - __bfloat162float(h));
        *(__nv_bfloat16*)(sm + SB2 + n*1040 + k*2) = h;
        *(__nv_bfloat16*)(sm + SB2L + n*1040 + k*2) = l;
    }
    __syncthreads();

    const int b0r = w * 16 + gr, b1r = b0r + 8, arow = b0r;
    const int uc = u0 + tig * 2;
    float h00 = 0.f, h01 = 0.f, h10 = 0.f, h11 = 0.f;
    float z00, z01, z10, z11;

    for (int t = 0; t < 512; t++) {
        float a1[2][4] = {{0,0,0,0},{0,0,0,0}};
        mma_phase<2>(sm, g_hhi, SB1, SB1L, a1, tid, arow, gr, tig);
        {
            const float* x0 = g_xproj + ((size_t)t * 128 + b0r) * 1536 + uc;
            const float* x1 = g_xproj + ((size_t)t * 128 + b1r) * 1536 + uc;
            float2 xz0 = *(const float2*)x0, xr0 = *(const float2*)(x0 + 512);
            float2 xz1 = *(const float2*)x1, xr1 = *(const float2*)(x1 + 512);
            z00 = hsig(xz0.x + a1[0][0]); z01 = hsig(xz0.y + a1[0][1]);
            z10 = hsig(xz1.x + a1[0][2]); z11 = hsig(xz1.y + a1[0][3]);
            float r00 = hsig(xr0.x + a1[1][0]), r01 = hsig(xr0.y + a1[1][1]);
            float r10 = hsig(xr1.x + a1[1][2]), r11 = hsig(xr1.y + a1[1][3]);
            wr_hi(g_rhhi, b0r * 512 + uc, r00 * h00, r01 * h01);
            wr_hi(g_rhhi, b1r * 512 + uc, r10 * h10, r11 * h11);
        }
        gbar(tid, 2 * t + 1);

        float a2[1][4] = {{0,0,0,0}};
        mma_phase<1>(sm, g_rhhi, SB2, SB2L, a2, tid, arow, gr, tig);
        {
            const float* x0 = g_xproj + ((size_t)t * 128 + b0r) * 1536 + 1024 + uc;
            const float* x1 = g_xproj + ((size_t)t * 128 + b1r) * 1536 + 1024 + uc;
            float2 xh0 = *(const float2*)x0, xh1 = *(const float2*)x1;
            float av0 = attn[b0r * 512 + t], av1 = attn[b1r * 512 + t];
            float hh;
            hh = tanhf(xh0.x + a2[0][0]); hh = z00 * h00 + (1.f - z00) * hh; h00 = av0 * hh + (1.f - av0) * h00;
            hh = tanhf(xh0.y + a2[0][1]); hh = z01 * h01 + (1.f - z01) * hh; h01 = av0 * hh + (1.f - av0) * h01;
            hh = tanhf(xh1.x + a2[0][2]); hh = z10 * h10 + (1.f - z10) * hh; h10 = av1 * hh + (1.f - av1) * h10;
            hh = tanhf(xh1.y + a2[0][3]); hh = z11 * h11 + (1.f - z11) * hh; h11 = av1 * hh + (1.f - av1) * h11;
            wr_hi(g_hhi, b0r * 512 + uc, h00, h01);
            wr_hi(g_hhi, b1r * 512 + uc, h10, h11);
            if (t == 511) {
                *(float2*)(out + b0r * 512 + uc) = make_float2(h00, h01);
                *(float2*)(out + b1r * 512 + uc) = make_float2(h10, h11);
            }
        }
        gbar(tid, 2 * t + 2);
    }
}

extern "C" void kernel_launch(void* const* d_in, const int* in_sizes, int n_in,
                              void* d_out, int out_size) {
    cudaFuncSetAttribute(rec_k, cudaFuncAttributeMaxDynamicSharedMemorySize, SMEM_TOT);
    init_k<<<256, 256>>>((const float*)d_in[1]);
    xproj_k<<<dim3(512, 12), 256>>>((const float*)d_in[0], (const float*)d_in[2], (const float*)d_in[4]);
    rec_k<<<NCTA, 256, SMEM_TOT>>>((const float*)d_in[3], (const float*)d_in[1], (float*)d_out);
}